// round 1
// baseline (speedup 1.0000x reference)
#include <cuda_runtime.h>

// ---------------- Problem constants ----------------
// B=4, N=4096, DIM=1024, HEADS=8, DH=64, BSZ=16, INNER=512
// M_ROWS = B*N = 16384, QKV width = 1536
// Levels 0..7. Pooled rows (levels 1..7): 2048+1024+...+32 = 4064
// Y/A rows (levels 0..7): 4096+...+32 = 8160

#define NROWS   16384
#define QKVW    1536
#define POOLROWS 4064
#define YROWS    8160

// ---------------- Device scratch (static; no allocations) ----------------
__device__ float g_qkv[(size_t)NROWS * QKVW];            // 25.2M floats
__device__ float g_poolq[(size_t)32 * POOLROWS * 64];
__device__ float g_poolk[(size_t)32 * POOLROWS * 64];
__device__ float g_poolv[(size_t)32 * POOLROWS * 64];
__device__ float g_Y[(size_t)32 * YROWS * 64];
__device__ float g_Asum[(size_t)32 * YROWS];
__device__ float g_att[(size_t)NROWS * 512];

// ---------------- SGEMM: C[M,N] = A[M,K] * B[N,K]^T (+bias) ----------------
// Both A and B are row-major with K contiguous. 128x128x16 tile, 8x8 per thread.
template <int BIAS>
__global__ __launch_bounds__(256)
void sgemm_nt(const float* __restrict__ A, const float* __restrict__ B,
              const float* __restrict__ bias, float* __restrict__ C,
              int M, int N, int K)
{
    const int BM = 128, BN = 128, BK = 16;
    __shared__ __align__(16) float As[BK][BM + 4];
    __shared__ __align__(16) float Bs[BK][BN + 4];

    int tx = threadIdx.x & 15;
    int ty = threadIdx.x >> 4;
    int row0 = blockIdx.y * BM;
    int col0 = blockIdx.x * BN;

    const float* Ab = A + (size_t)row0 * K;
    const float* Bb = B + (size_t)col0 * K;

    float acc[8][8];
#pragma unroll
    for (int i = 0; i < 8; i++)
#pragma unroll
        for (int j = 0; j < 8; j++) acc[i][j] = 0.f;

    for (int k0 = 0; k0 < K; k0 += BK) {
#pragma unroll
        for (int i = 0; i < 2; i++) {
            int s  = threadIdx.x + i * 256;   // 512 float4 slots
            int r  = s >> 2;
            int kq = (s & 3) * 4;
            float4 va = *(const float4*)(Ab + (size_t)r * K + k0 + kq);
            As[kq + 0][r] = va.x; As[kq + 1][r] = va.y;
            As[kq + 2][r] = va.z; As[kq + 3][r] = va.w;
            float4 vb = *(const float4*)(Bb + (size_t)r * K + k0 + kq);
            Bs[kq + 0][r] = vb.x; Bs[kq + 1][r] = vb.y;
            Bs[kq + 2][r] = vb.z; Bs[kq + 3][r] = vb.w;
        }
        __syncthreads();

#pragma unroll
        for (int kk = 0; kk < BK; kk++) {
            float a[8], b[8];
            *(float4*)(a)     = *(const float4*)&As[kk][ty * 8];
            *(float4*)(a + 4) = *(const float4*)&As[kk][ty * 8 + 4];
            *(float4*)(b)     = *(const float4*)&Bs[kk][tx * 8];
            *(float4*)(b + 4) = *(const float4*)&Bs[kk][tx * 8 + 4];
#pragma unroll
            for (int i = 0; i < 8; i++)
#pragma unroll
                for (int j = 0; j < 8; j++)
                    acc[i][j] += a[i] * b[j];
        }
        __syncthreads();
    }

#pragma unroll
    for (int ii = 0; ii < 8; ii++) {
        size_t row = (size_t)(row0 + ty * 8 + ii);
        float* Cp = C + row * N + col0 + tx * 8;
#pragma unroll
        for (int jj = 0; jj < 8; jj += 4) {
            float4 v = make_float4(acc[ii][jj], acc[ii][jj + 1],
                                   acc[ii][jj + 2], acc[ii][jj + 3]);
            if (BIAS) {
                const float* bp = bias + col0 + tx * 8 + jj;
                v.x += bp[0]; v.y += bp[1]; v.z += bp[2]; v.w += bp[3];
            }
            *(float4*)(Cp + jj) = v;
        }
    }
}

// ---------------- Pooling ----------------
// Level 1 directly from qkv (q gets the DIM_HEAD^-0.5 = 0.125 scale folded in).
__global__ void pool_l1(const float* __restrict__ qkv)
{
    int tid = blockIdx.x * blockDim.x + threadIdx.x;   // 32*2048*64 threads
    int d  = tid & 63;
    int i  = (tid >> 6) & 2047;
    int bh = tid >> 17;
    int b = bh >> 3, h = bh & 7;
    size_t base = ((size_t)(b * 4096 + 2 * i)) * QKVW + h * 64 + d;
    float q = 0.0625f * (qkv[base] + qkv[base + QKVW]);                   // mean of 0.125-scaled
    float k = 0.5f * (qkv[base + 512] + qkv[base + 512 + QKVW]);
    float v = qkv[base + 1024] + qkv[base + 1024 + QKVW];
    size_t dst = (size_t)bh * (POOLROWS * 64) + (size_t)i * 64 + d;
    g_poolq[dst] = q; g_poolk[dst] = k; g_poolv[dst] = v;
}

// Levels 2..7 from previous pooled level.
__global__ void pool_step(int n, int srcOff, int dstOff)
{
    int tid = blockIdx.x * blockDim.x + threadIdx.x;   // 32*n*64 threads (exact)
    int d  = tid & 63;
    int i  = (tid >> 6) % n;
    int bh = tid / (n * 64);
    size_t sb = (size_t)bh * (POOLROWS * 64) + (size_t)(srcOff + 2 * i) * 64 + d;
    size_t db = (size_t)bh * (POOLROWS * 64) + (size_t)(dstOff + i) * 64 + d;
    g_poolq[db] = 0.5f * (g_poolq[sb] + g_poolq[sb + 64]);
    g_poolk[db] = 0.5f * (g_poolk[sb] + g_poolk[sb + 64]);
    g_poolv[db] = g_poolv[sb] + g_poolv[sb + 64];
}

// ---------------- Block attention ----------------
// One warp per 16x16 attention block. 510 blocks per bh (levels 0..7),
// 16320 warps total. Keys of coarse levels use sibling flip: kblk = blk ^ 1.
__global__ __launch_bounds__(128)
void attn_blocks(const float* __restrict__ qkv)
{
    __shared__ __align__(16) float sk[4][16 * 68];
    __shared__ __align__(16) float sv[4][16 * 68];
    int warp = threadIdx.x >> 5;
    int lane = threadIdx.x & 31;
    int wg = blockIdx.x * 4 + warp;          // [0, 16320)

    int bh = wg / 510;
    int r  = wg - bh * 510;
    int level = 0, nb = 256;
    while (r >= nb) { r -= nb; nb >>= 1; level++; }
    int blk = r;
    int b = bh >> 3, h = bh & 7;
    int kblk = (level == 0) ? blk : (blk ^ 1);

    float* ks = sk[warp];
    float* vs = sv[warp];

    // Stage k (flipped block) and v (own block) into smem.
    if (level == 0) {
        for (int idx = lane; idx < 1024; idx += 32) {
            int j = idx >> 6, d = idx & 63;
            size_t gk = ((size_t)(b * 4096 + kblk * 16 + j)) * QKVW + h * 64 + d;
            size_t gv = ((size_t)(b * 4096 + blk  * 16 + j)) * QKVW + h * 64 + d;
            ks[j * 68 + d] = qkv[gk + 512];
            vs[j * 68 + d] = qkv[gv + 1024];
        }
    } else {
        int off = 4096 - (8192 >> level);
        const float* kp = g_poolk + (size_t)bh * (POOLROWS * 64) + (size_t)(off + kblk * 16) * 64;
        const float* vp = g_poolv + (size_t)bh * (POOLROWS * 64) + (size_t)(off + blk  * 16) * 64;
        for (int idx = lane; idx < 1024; idx += 32) {
            int j = idx >> 6, d = idx & 63;
            ks[j * 68 + d] = kp[idx];
            vs[j * 68 + d] = vp[idx];
        }
    }

    // q half-row in registers: lane pair (2i, 2i+1) shares query row i.
    int qi = lane >> 1, hh = lane & 1, dbase = hh * 32;
    float qr[32];
    if (level == 0) {
        const float* qp = qkv + ((size_t)(b * 4096 + blk * 16 + qi)) * QKVW + h * 64 + dbase;
#pragma unroll
        for (int t = 0; t < 32; t++) qr[t] = 0.125f * qp[t];
    } else {
        int off = 4096 - (8192 >> level);
        const float* qp = g_poolq + (size_t)bh * (POOLROWS * 64)
                        + (size_t)(off + blk * 16 + qi) * 64 + dbase;
#pragma unroll
        for (int t = 0; t < 32; t++) qr[t] = qp[t];
    }
    __syncwarp();

    // S row: each lane does half-dim partial dots for all 16 keys; exchange
    // with partner lane to get the full dot. Both lanes hold full A row.
    float Aij[16];
#pragma unroll
    for (int j = 0; j < 16; j++) {
        float p = 0.f;
        const float* kr = ks + j * 68 + dbase;
#pragma unroll
        for (int t = 0; t < 32; t++) p += qr[t] * kr[t];
        p += __shfl_xor_sync(0xffffffffu, p, 1);
        Aij[j] = expf(p);
    }
    float asum = 0.f;
#pragma unroll
    for (int j = 0; j < 16; j++) asum += Aij[j];

    // y = A @ v ; each lane accumulates its 32-d half.
    float ya[32];
#pragma unroll
    for (int t = 0; t < 32; t++) ya[t] = 0.f;
#pragma unroll
    for (int j = 0; j < 16; j++) {
        float a = Aij[j];
        const float* vr = vs + j * 68 + dbase;
#pragma unroll
        for (int t = 0; t < 32; t++) ya[t] += a * vr[t];
    }

    int yoff = 8192 - (8192 >> level);
    size_t yrow = (size_t)bh * (YROWS * 64) + (size_t)(yoff + blk * 16 + qi) * 64 + dbase;
#pragma unroll
    for (int t = 0; t < 32; t++) g_Y[yrow + t] = ya[t];
    if (hh == 0)
        g_Asum[(size_t)bh * YROWS + yoff + blk * 16 + qi] = asum;
}

// ---------------- Combine levels + normalize + relayout to (b n) x (h d) ----
__global__ void combine_kernel()
{
    int tid = blockIdx.x * blockDim.x + threadIdx.x;   // 16384*512 threads
    int c = tid & 511;
    int m = tid >> 9;
    int h = c >> 6, d = c & 63;
    int b = m >> 12, n = m & 4095;
    int bh = b * 8 + h;

    float ysum = 0.f, asum = 0.f;
#pragma unroll
    for (int l = 0; l < 8; l++) {
        int yoff = 8192 - (8192 >> l);
        int p = n >> l;
        ysum += g_Y[(size_t)bh * (YROWS * 64) + (size_t)(yoff + p) * 64 + d];
        asum += g_Asum[(size_t)bh * YROWS + yoff + p];
    }
    g_att[tid] = ysum / (asum + 1e-8f);
}

// ---------------- Launch ----------------
extern "C" void kernel_launch(void* const* d_in, const int* in_sizes, int n_in,
                              void* d_out, int out_size)
{
    const float* x     = (const float*)d_in[0];   // [4,4096,1024]
    const float* w_qkv = (const float*)d_in[1];   // [1536,1024]
    const float* w_out = (const float*)d_in[2];   // [1024,512]
    const float* b_out = (const float*)d_in[3];   // [1024]
    float* out = (float*)d_out;                   // [4,4096,1024]

    float *qkv_ptr, *att_ptr;
    cudaGetSymbolAddress((void**)&qkv_ptr, g_qkv);
    cudaGetSymbolAddress((void**)&att_ptr, g_att);

    // 1) QKV projection: [16384,1024] x [1536,1024]^T -> [16384,1536]
    {
        dim3 grid(QKVW / 128, NROWS / 128);
        sgemm_nt<0><<<grid, 256>>>(x, w_qkv, nullptr, qkv_ptr, NROWS, QKVW, 1024);
    }

    // 2) Pooling levels 1..7
    pool_l1<<<(32 * 2048 * 64) / 256, 256>>>(qkv_ptr);
    for (int l = 2; l <= 7; l++) {
        int n = 4096 >> l;
        pool_step<<<(32 * n * 64) / 256, 256>>>(n, 4096 - (8192 >> (l - 1)),
                                                4096 - (8192 >> l));
    }

    // 3) Block attention over all levels (16320 warps, 4 warps/CTA)
    attn_blocks<<<4080, 128>>>(qkv_ptr);

    // 4) Combine + normalize + relayout
    combine_kernel<<<(NROWS * 512) / 256, 256>>>();

    // 5) Output projection: [16384,512] x [1024,512]^T + bias -> [16384,1024]
    {
        dim3 grid(1024 / 128, NROWS / 128);
        sgemm_nt<1><<<grid, 256>>>(att_ptr, w_out, b_out, out, NROWS, 1024, 512);
    }
}

// round 3
// speedup vs baseline: 1.7700x; 1.7700x over previous
#include <cuda_runtime.h>
#include <cuda_bf16.h>
#include <cstdint>

// ---------------- Problem constants ----------------
#define NROWS   16384
#define QKVW    1536
#define POOLROWS 4064
#define YROWS    8160

// ---------------- Device scratch ----------------
__device__ float g_qkv[(size_t)NROWS * QKVW];
__device__ float g_poolq[(size_t)32 * POOLROWS * 64];
__device__ float g_poolk[(size_t)32 * POOLROWS * 64];
__device__ float g_poolv[(size_t)32 * POOLROWS * 64];
__device__ float g_Y[(size_t)32 * YROWS * 64];
__device__ float g_Asum[(size_t)32 * YROWS];
__device__ float g_att[(size_t)NROWS * 512];

// ---------------- helpers ----------------
__device__ __forceinline__ uint32_t smem_to_u32(const void* p) {
    uint32_t a;
    asm("{ .reg .u64 t; cvta.to.shared.u64 t, %1; cvt.u32.u64 %0, t; }" : "=r"(a) : "l"(p));
    return a;
}
__device__ __forceinline__ uint32_t sw128(uint32_t off) {
    return off ^ ((off >> 3) & 0x70);
}

#define LDSM_X4(r0, r1, r2, r3, addr) \
    asm volatile("ldmatrix.sync.aligned.m8n8.x4.shared.b16 {%0,%1,%2,%3}, [%4];" \
        : "=r"(r0), "=r"(r1), "=r"(r2), "=r"(r3) : "r"(addr))

__device__ __forceinline__ void mma16816(float* c, const uint32_t* a, const uint32_t* b) {
    asm volatile(
        "mma.sync.aligned.m16n8k16.row.col.f32.bf16.bf16.f32 "
        "{%0,%1,%2,%3}, {%4,%5,%6,%7}, {%8,%9}, {%0,%1,%2,%3};"
        : "+f"(c[0]), "+f"(c[1]), "+f"(c[2]), "+f"(c[3])
        : "r"(a[0]), "r"(a[1]), "r"(a[2]), "r"(a[3]), "r"(b[0]), "r"(b[1]));
}

// fp32 quad -> bf16 hi/lo packed pairs
__device__ __forceinline__ void split4(float4 v, uint2& hi, uint2& lo) {
    float f[4] = {v.x, v.y, v.z, v.w};
    uint32_t h[4], l[4];
#pragma unroll
    for (int i = 0; i < 4; i++) {
        __nv_bfloat16 hb = __float2bfloat16_rn(f[i]);
        float res = f[i] - __bfloat162float(hb);
        __nv_bfloat16 lb = __float2bfloat16_rn(res);
        h[i] = (uint32_t)__bfloat16_as_ushort(hb);
        l[i] = (uint32_t)__bfloat16_as_ushort(lb);
    }
    hi.x = h[0] | (h[1] << 16); hi.y = h[2] | (h[3] << 16);
    lo.x = l[0] | (l[1] << 16); lo.y = l[2] | (l[3] << 16);
}

// ---------------- mma.sync GEMM: C[M,N] = A[M,K]*B[N,K]^T (+bias) ---------
// 128x128 CTA tile, BK=64. 8 warps (2m x 4n), warp tile 64x32.
// 3-term bf16 hi/lo split for fp32-grade accuracy.
// Stage layout (64KB): Ah[128][64]bf16 @0, Al @16384, Bh @32768, Bl @49152.
#define GS_STAGE 65536
#define GS_SMEM  (2 * GS_STAGE)

template <int BIAS>
__global__ __launch_bounds__(256, 1)
void gemm_mma(const float* __restrict__ A, const float* __restrict__ Bw,
              const float* __restrict__ bias, float* __restrict__ C,
              int M, int N, int K)
{
    extern __shared__ __align__(1024) char smem[];
    const uint32_t smu = smem_to_u32(smem);
    const int tid = threadIdx.x;
    const int wid = tid >> 5, lane = tid & 31;
    const int warpM = wid & 1, warpN = wid >> 1;
    const int row0 = blockIdx.y * 128;
    const int col0 = blockIdx.x * 128;
    const int KS = K >> 6;

    float acc[4][4][4];
#pragma unroll
    for (int i = 0; i < 4; i++)
#pragma unroll
        for (int j = 0; j < 4; j++)
#pragma unroll
            for (int t = 0; t < 4; t++) acc[i][j][t] = 0.f;

    const float* Abase = A + (size_t)row0 * K;
    const float* Bbase = Bw + (size_t)col0 * K;

    auto ldg_tile = [&](const float* G, int ks, float4* r) {
        const float* Gp = G + ks * 64;
#pragma unroll
        for (int i = 0; i < 8; i++) {
            int f = tid + (i << 8);
            int rr = f >> 4, q = f & 15;
            r[i] = *(const float4*)(Gp + (size_t)rr * K + (q << 2));
        }
    };
    auto sts_tile = [&](char* st, int regionOff, const float4* r) {
#pragma unroll
        for (int i = 0; i < 8; i++) {
            int f = tid + (i << 8);
            int rr = f >> 4, q = f & 15;
            uint2 hi, lo; split4(r[i], hi, lo);
            uint32_t off = sw128((uint32_t)(rr * 128 + (q << 3)));
            *(uint2*)(st + regionOff + off) = hi;
            *(uint2*)(st + regionOff + 16384 + off) = lo;
        }
    };

    auto compute_k16 = [&](uint32_t sbase, int kk) {
        uint32_t ah[4][4], al[4][4], bh[2][4], bl[2][4];
        int aRow = warpM * 64 + (lane & 15);
        int aK2 = (kk * 16 + ((lane & 16) ? 8 : 0)) * 2;
#pragma unroll
        for (int mt = 0; mt < 4; mt++) {
            uint32_t off = sw128((uint32_t)((aRow + mt * 16) * 128 + aK2));
            LDSM_X4(ah[mt][0], ah[mt][1], ah[mt][2], ah[mt][3], sbase + off);
            LDSM_X4(al[mt][0], al[mt][1], al[mt][2], al[mt][3], sbase + 16384 + off);
        }
        int bRow = warpN * 32 + (lane & 7) + ((lane & 16) ? 8 : 0);
        int bK2 = (kk * 16 + ((lane & 8) ? 8 : 0)) * 2;
#pragma unroll
        for (int pr = 0; pr < 2; pr++) {
            uint32_t off = sw128((uint32_t)((bRow + pr * 16) * 128 + bK2));
            LDSM_X4(bh[pr][0], bh[pr][1], bh[pr][2], bh[pr][3], sbase + 32768 + off);
            LDSM_X4(bl[pr][0], bl[pr][1], bl[pr][2], bl[pr][3], sbase + 49152 + off);
        }
#pragma unroll
        for (int mt = 0; mt < 4; mt++)
#pragma unroll
            for (int nt = 0; nt < 4; nt++) {
                const uint32_t* bhp = &bh[nt >> 1][(nt & 1) * 2];
                const uint32_t* blp = &bl[nt >> 1][(nt & 1) * 2];
                mma16816(acc[mt][nt], ah[mt], bhp);
                mma16816(acc[mt][nt], ah[mt], blp);
                mma16816(acc[mt][nt], al[mt], bhp);
            }
    };

    float4 rA[8], rB[8];
    ldg_tile(Abase, 0, rA);
    ldg_tile(Bbase, 0, rB);
    sts_tile(smem, 0, rA);
    sts_tile(smem, 32768, rB);
    __syncthreads();

    for (int ks = 0; ks < KS; ks++) {
        uint32_t sbase = smu + (uint32_t)(ks & 1) * GS_STAGE;
        char* stNext = smem + ((ks & 1) ^ 1) * GS_STAGE;
        bool more = (ks + 1) < KS;
        if (more) ldg_tile(Abase, ks + 1, rA);
        compute_k16(sbase, 0);
        if (more) { sts_tile(stNext, 0, rA); ldg_tile(Bbase, ks + 1, rB); }
        compute_k16(sbase, 1);
        compute_k16(sbase, 2);
        if (more) sts_tile(stNext, 32768, rB);
        compute_k16(sbase, 3);
        __syncthreads();
    }

    // Epilogue
    int mBase = row0 + warpM * 64 + (lane >> 2);
    int nBase = col0 + warpN * 32 + (lane & 3) * 2;
#pragma unroll
    for (int mt = 0; mt < 4; mt++)
#pragma unroll
        for (int nt = 0; nt < 4; nt++) {
            int m = mBase + mt * 16;
            int n = nBase + nt * 8;
            float2 v0 = make_float2(acc[mt][nt][0], acc[mt][nt][1]);
            float2 v1 = make_float2(acc[mt][nt][2], acc[mt][nt][3]);
            if (BIAS) {
                float b0 = bias[n], b1 = bias[n + 1];
                v0.x += b0; v0.y += b1; v1.x += b0; v1.y += b1;
            }
            *(float2*)(C + (size_t)m * N + n) = v0;
            *(float2*)(C + (size_t)(m + 8) * N + n) = v1;
        }
}

// ---------------- Pooling ----------------
__global__ void pool_l1(const float* __restrict__ qkv)
{
    int tid = blockIdx.x * blockDim.x + threadIdx.x;
    int d  = tid & 63;
    int i  = (tid >> 6) & 2047;
    int bh = tid >> 17;
    int b = bh >> 3, h = bh & 7;
    size_t base = ((size_t)(b * 4096 + 2 * i)) * QKVW + h * 64 + d;
    float q = 0.0625f * (qkv[base] + qkv[base + QKVW]);
    float k = 0.5f * (qkv[base + 512] + qkv[base + 512 + QKVW]);
    float v = qkv[base + 1024] + qkv[base + 1024 + QKVW];
    size_t dst = (size_t)bh * (POOLROWS * 64) + (size_t)i * 64 + d;
    g_poolq[dst] = q; g_poolk[dst] = k; g_poolv[dst] = v;
}

__global__ void pool_step(int n, int srcOff, int dstOff)
{
    int tid = blockIdx.x * blockDim.x + threadIdx.x;
    int d  = tid & 63;
    int i  = (tid >> 6) % n;
    int bh = tid / (n * 64);
    size_t sb_ = (size_t)bh * (POOLROWS * 64) + (size_t)(srcOff + 2 * i) * 64 + d;
    size_t db = (size_t)bh * (POOLROWS * 64) + (size_t)(dstOff + i) * 64 + d;
    g_poolq[db] = 0.5f * (g_poolq[sb_] + g_poolq[sb_ + 64]);
    g_poolk[db] = 0.5f * (g_poolk[sb_] + g_poolk[sb_ + 64]);
    g_poolv[db] = g_poolv[sb_] + g_poolv[sb_ + 64];
}

// ---------------- Block attention ----------------
__global__ __launch_bounds__(128)
void attn_blocks(const float* __restrict__ qkv)
{
    __shared__ __align__(16) float sk[4][16 * 68];
    __shared__ __align__(16) float sv[4][16 * 68];
    int warp = threadIdx.x >> 5;
    int lane = threadIdx.x & 31;
    int wg = blockIdx.x * 4 + warp;

    int bh = wg / 510;
    int r  = wg - bh * 510;
    int level = 0, nb = 256;
    while (r >= nb) { r -= nb; nb >>= 1; level++; }
    int blk = r;
    int b = bh >> 3, h = bh & 7;
    int kblk = (level == 0) ? blk : (blk ^ 1);

    float* ks = sk[warp];
    float* vs = sv[warp];

    if (level == 0) {
        for (int idx = lane; idx < 1024; idx += 32) {
            int j = idx >> 6, d = idx & 63;
            size_t gk = ((size_t)(b * 4096 + kblk * 16 + j)) * QKVW + h * 64 + d;
            size_t gv = ((size_t)(b * 4096 + blk  * 16 + j)) * QKVW + h * 64 + d;
            ks[j * 68 + d] = qkv[gk + 512];
            vs[j * 68 + d] = qkv[gv + 1024];
        }
    } else {
        int off = 4096 - (8192 >> level);
        const float* kp = g_poolk + (size_t)bh * (POOLROWS * 64) + (size_t)(off + kblk * 16) * 64;
        const float* vp = g_poolv + (size_t)bh * (POOLROWS * 64) + (size_t)(off + blk  * 16) * 64;
        for (int idx = lane; idx < 1024; idx += 32) {
            int j = idx >> 6, d = idx & 63;
            ks[j * 68 + d] = kp[idx];
            vs[j * 68 + d] = vp[idx];
        }
    }

    int qi = lane >> 1, hh = lane & 1, dbase = hh * 32;
    float qr[32];
    if (level == 0) {
        const float* qp = qkv + ((size_t)(b * 4096 + blk * 16 + qi)) * QKVW + h * 64 + dbase;
#pragma unroll
        for (int t = 0; t < 32; t++) qr[t] = 0.125f * qp[t];
    } else {
        int off = 4096 - (8192 >> level);
        const float* qp = g_poolq + (size_t)bh * (POOLROWS * 64)
                        + (size_t)(off + blk * 16 + qi) * 64 + dbase;
#pragma unroll
        for (int t = 0; t < 32; t++) qr[t] = qp[t];
    }
    __syncwarp();

    float Aij[16];
#pragma unroll
    for (int j = 0; j < 16; j++) {
        float p = 0.f;
        const float* kr = ks + j * 68 + dbase;
#pragma unroll
        for (int t = 0; t < 32; t++) p += qr[t] * kr[t];
        p += __shfl_xor_sync(0xffffffffu, p, 1);
        Aij[j] = expf(p);
    }
    float asum = 0.f;
#pragma unroll
    for (int j = 0; j < 16; j++) asum += Aij[j];

    float ya[32];
#pragma unroll
    for (int t = 0; t < 32; t++) ya[t] = 0.f;
#pragma unroll
    for (int j = 0; j < 16; j++) {
        float a = Aij[j];
        const float* vr = vs + j * 68 + dbase;
#pragma unroll
        for (int t = 0; t < 32; t++) ya[t] += a * vr[t];
    }

    int yoff = 8192 - (8192 >> level);
    size_t yrow = (size_t)bh * (YROWS * 64) + (size_t)(yoff + blk * 16 + qi) * 64 + dbase;
#pragma unroll
    for (int t = 0; t < 32; t++) g_Y[yrow + t] = ya[t];
    if (hh == 0)
        g_Asum[(size_t)bh * YROWS + yoff + blk * 16 + qi] = asum;
}

// ---------------- Combine ----------------
__global__ void combine_kernel()
{
    int tid = blockIdx.x * blockDim.x + threadIdx.x;
    int c = tid & 511;
    int m = tid >> 9;
    int h = c >> 6, d = c & 63;
    int b = m >> 12, n = m & 4095;
    int bh = b * 8 + h;

    float ysum = 0.f, asum = 0.f;
#pragma unroll
    for (int l = 0; l < 8; l++) {
        int yoff = 8192 - (8192 >> l);
        int p = n >> l;
        ysum += g_Y[(size_t)bh * (YROWS * 64) + (size_t)(yoff + p) * 64 + d];
        asum += g_Asum[(size_t)bh * YROWS + yoff + p];
    }
    g_att[tid] = ysum / (asum + 1e-8f);
}

// ---------------- Launch ----------------
extern "C" void kernel_launch(void* const* d_in, const int* in_sizes, int n_in,
                              void* d_out, int out_size)
{
    const float* x     = (const float*)d_in[0];
    const float* w_qkv = (const float*)d_in[1];
    const float* w_out = (const float*)d_in[2];
    const float* b_out = (const float*)d_in[3];
    float* out = (float*)d_out;

    float *qkv_ptr, *att_ptr;
    cudaGetSymbolAddress((void**)&qkv_ptr, g_qkv);
    cudaGetSymbolAddress((void**)&att_ptr, g_att);

    cudaFuncSetAttribute(gemm_mma<0>, cudaFuncAttributeMaxDynamicSharedMemorySize, GS_SMEM);
    cudaFuncSetAttribute(gemm_mma<1>, cudaFuncAttributeMaxDynamicSharedMemorySize, GS_SMEM);

    // 1) QKV projection: [16384,1024] x [1536,1024]^T -> [16384,1536]
    gemm_mma<0><<<dim3(QKVW / 128, NROWS / 128), 256, GS_SMEM>>>(
        x, w_qkv, nullptr, qkv_ptr, NROWS, QKVW, 1024);

    // 2) Pooling levels 1..7
    pool_l1<<<(32 * 2048 * 64) / 256, 256>>>(qkv_ptr);
    for (int l = 2; l <= 7; l++) {
        int n = 4096 >> l;
        pool_step<<<(32 * n * 64) / 256, 256>>>(n, 4096 - (8192 >> (l - 1)),
                                                4096 - (8192 >> l));
    }

    // 3) Block attention
    attn_blocks<<<4080, 128>>>(qkv_ptr);

    // 4) Combine + normalize + relayout
    combine_kernel<<<(NROWS * 512) / 256, 256>>>();

    // 5) Output projection: [16384,512] x [1024,512]^T + bias -> [16384,1024]
    gemm_mma<1><<<dim3(1024 / 128, NROWS / 128), 256, GS_SMEM>>>(
        att_ptr, w_out, b_out, out, NROWS, 1024, 512);
}

// round 4
// speedup vs baseline: 2.2926x; 1.2953x over previous
#include <cuda_runtime.h>
#include <cuda_bf16.h>
#include <cstdint>

// ---------------- Problem constants ----------------
#define NROWS   16384
#define QKVW    1536
#define POOLROWS 4064
#define YROWS    8160

// ---------------- Device scratch ----------------
__device__ float g_qkv[(size_t)NROWS * QKVW];
__device__ float g_poolq[(size_t)32 * POOLROWS * 64];
__device__ float g_poolk[(size_t)32 * POOLROWS * 64];
__device__ float g_poolv[(size_t)32 * POOLROWS * 64];
__device__ float g_Y[(size_t)32 * YROWS * 64];
__device__ float g_Asum[(size_t)32 * YROWS];

// bf16 hi/lo planes
__device__ __nv_bfloat16 g_xh[(size_t)NROWS * 1024];
__device__ __nv_bfloat16 g_xl[(size_t)NROWS * 1024];
__device__ __nv_bfloat16 g_wqh[(size_t)QKVW * 1024];
__device__ __nv_bfloat16 g_wql[(size_t)QKVW * 1024];
__device__ __nv_bfloat16 g_woh[(size_t)1024 * 512];
__device__ __nv_bfloat16 g_wol[(size_t)1024 * 512];
__device__ __nv_bfloat16 g_atth[(size_t)NROWS * 512];
__device__ __nv_bfloat16 g_attl[(size_t)NROWS * 512];

// ---------------- helpers ----------------
__device__ __forceinline__ uint32_t smem_to_u32(const void* p) {
    uint32_t a;
    asm("{ .reg .u64 t; cvta.to.shared.u64 t, %1; cvt.u32.u64 %0, t; }" : "=r"(a) : "l"(p));
    return a;
}
__device__ __forceinline__ uint32_t sw128(uint32_t off) {
    return off ^ ((off >> 3) & 0x70);
}

#define LDSM_X4(r0, r1, r2, r3, addr) \
    asm volatile("ldmatrix.sync.aligned.m8n8.x4.shared.b16 {%0,%1,%2,%3}, [%4];" \
        : "=r"(r0), "=r"(r1), "=r"(r2), "=r"(r3) : "r"(addr))

__device__ __forceinline__ void mma16816(float* c, const uint32_t* a, const uint32_t* b) {
    asm volatile(
        "mma.sync.aligned.m16n8k16.row.col.f32.bf16.bf16.f32 "
        "{%0,%1,%2,%3}, {%4,%5,%6,%7}, {%8,%9}, {%0,%1,%2,%3};"
        : "+f"(c[0]), "+f"(c[1]), "+f"(c[2]), "+f"(c[3])
        : "r"(a[0]), "r"(a[1]), "r"(a[2]), "r"(a[3]), "r"(b[0]), "r"(b[1]));
}

__device__ __forceinline__ void split4(float4 v, uint2& hi, uint2& lo) {
    float f[4] = {v.x, v.y, v.z, v.w};
    uint32_t h[4], l[4];
#pragma unroll
    for (int i = 0; i < 4; i++) {
        __nv_bfloat16 hb = __float2bfloat16_rn(f[i]);
        float res = f[i] - __bfloat162float(hb);
        __nv_bfloat16 lb = __float2bfloat16_rn(res);
        h[i] = (uint32_t)__bfloat16_as_ushort(hb);
        l[i] = (uint32_t)__bfloat16_as_ushort(lb);
    }
    hi.x = h[0] | (h[1] << 16); hi.y = h[2] | (h[3] << 16);
    lo.x = l[0] | (l[1] << 16); lo.y = l[2] | (l[3] << 16);
}

// ---------------- one-shot fp32 -> bf16 hi/lo conversion ----------------
// quads: x 4194304 | w_qkv 393216 | w_out 131072
__global__ __launch_bounds__(256)
void convert_all(const float* __restrict__ x, const float* __restrict__ wq,
                 const float* __restrict__ wo)
{
    int q = blockIdx.x * 256 + threadIdx.x;
    const float* src;
    uint2 *dh, *dl;
    int local;
    if (q < 4194304) {
        src = x; dh = (uint2*)g_xh; dl = (uint2*)g_xl; local = q;
    } else if (q < 4194304 + 393216) {
        src = wq; dh = (uint2*)g_wqh; dl = (uint2*)g_wql; local = q - 4194304;
    } else {
        src = wo; dh = (uint2*)g_woh; dl = (uint2*)g_wol; local = q - 4194304 - 393216;
    }
    float4 v = *(const float4*)(src + (size_t)local * 4);
    uint2 hi, lo; split4(v, hi, lo);
    dh[local] = hi; dl[local] = lo;
}

// ---------------- mma.sync GEMM on preconverted planes ---------------------
// C[M,N] = A[M,K]*B[N,K]^T (+bias). 128x128 tile, BK=64, cp.async double buf.
// Stage (64KB): Ah @0, Al @16384, Bh @32768, Bl @49152 (bf16, SW128 rows of 64).
#define GS_STAGE 65536
#define GS_SMEM  (2 * GS_STAGE)

template <int BIAS>
__global__ __launch_bounds__(256, 1)
void gemm_bf16(const __nv_bfloat16* __restrict__ Ah, const __nv_bfloat16* __restrict__ Al,
               const __nv_bfloat16* __restrict__ Bh, const __nv_bfloat16* __restrict__ Bl,
               const float* __restrict__ bias, float* __restrict__ C,
               int M, int N, int K)
{
    extern __shared__ __align__(1024) char smem[];
    const uint32_t smu = smem_to_u32(smem);
    const int tid = threadIdx.x;
    const int wid = tid >> 5, lane = tid & 31;
    const int warpM = wid & 1, warpN = wid >> 1;
    const int row0 = blockIdx.y * 128;
    const int col0 = blockIdx.x * 128;
    const int KS = K >> 6;

    float acc[4][4][4];
#pragma unroll
    for (int i = 0; i < 4; i++)
#pragma unroll
        for (int j = 0; j < 4; j++)
#pragma unroll
            for (int t = 0; t < 4; t++) acc[i][j][t] = 0.f;

    auto prefetch = [&](int ks, int buf) {
        const __nv_bfloat16* gs[4] = {
            Ah + (size_t)row0 * K + ks * 64,
            Al + (size_t)row0 * K + ks * 64,
            Bh + (size_t)col0 * K + ks * 64,
            Bl + (size_t)col0 * K + ks * 64
        };
        uint32_t sb = smu + (uint32_t)buf * GS_STAGE;
        int q = tid & 7;
        int rbase = tid >> 3;
#pragma unroll
        for (int i = 0; i < 16; i++) {
            int plane = i >> 2;
            int r = ((i & 3) << 5) + rbase;
            const void* gp = gs[plane] + (size_t)r * K + q * 8;
            uint32_t sa = sb + plane * 16384 + sw128((uint32_t)(r * 128 + q * 16));
            asm volatile("cp.async.cg.shared.global [%0], [%1], 16;" :: "r"(sa), "l"(gp));
        }
    };

    auto compute_k16 = [&](uint32_t sbase, int kk) {
        uint32_t ah[4][4], al[4][4], bh[2][4], bl[2][4];
        int aRow = warpM * 64 + (lane & 15);
        int aK2 = (kk * 16 + ((lane & 16) ? 8 : 0)) * 2;
#pragma unroll
        for (int mt = 0; mt < 4; mt++) {
            uint32_t off = sw128((uint32_t)((aRow + mt * 16) * 128 + aK2));
            LDSM_X4(ah[mt][0], ah[mt][1], ah[mt][2], ah[mt][3], sbase + off);
            LDSM_X4(al[mt][0], al[mt][1], al[mt][2], al[mt][3], sbase + 16384 + off);
        }
        int bRow = warpN * 32 + (lane & 7) + ((lane & 16) ? 8 : 0);
        int bK2 = (kk * 16 + ((lane & 8) ? 8 : 0)) * 2;
#pragma unroll
        for (int pr = 0; pr < 2; pr++) {
            uint32_t off = sw128((uint32_t)((bRow + pr * 16) * 128 + bK2));
            LDSM_X4(bh[pr][0], bh[pr][1], bh[pr][2], bh[pr][3], sbase + 32768 + off);
            LDSM_X4(bl[pr][0], bl[pr][1], bl[pr][2], bl[pr][3], sbase + 49152 + off);
        }
#pragma unroll
        for (int mt = 0; mt < 4; mt++)
#pragma unroll
            for (int nt = 0; nt < 4; nt++) {
                const uint32_t* bhp = &bh[nt >> 1][(nt & 1) * 2];
                const uint32_t* blp = &bl[nt >> 1][(nt & 1) * 2];
                mma16816(acc[mt][nt], ah[mt], bhp);
                mma16816(acc[mt][nt], ah[mt], blp);
                mma16816(acc[mt][nt], al[mt], bhp);
            }
    };

    prefetch(0, 0);
    asm volatile("cp.async.commit_group;" ::: "memory");
    prefetch(1, 1);
    asm volatile("cp.async.commit_group;" ::: "memory");

    for (int ks = 0; ks < KS; ks++) {
        asm volatile("cp.async.wait_group 1;" ::: "memory");
        __syncthreads();
        uint32_t sbase = smu + (uint32_t)(ks & 1) * GS_STAGE;
#pragma unroll
        for (int kk = 0; kk < 4; kk++) compute_k16(sbase, kk);
        __syncthreads();
        if (ks + 2 < KS) prefetch(ks + 2, ks & 1);
        asm volatile("cp.async.commit_group;" ::: "memory");
    }

    int mBase = row0 + warpM * 64 + (lane >> 2);
    int nBase = col0 + warpN * 32 + (lane & 3) * 2;
#pragma unroll
    for (int mt = 0; mt < 4; mt++)
#pragma unroll
        for (int nt = 0; nt < 4; nt++) {
            int m = mBase + mt * 16;
            int n = nBase + nt * 8;
            float2 v0 = make_float2(acc[mt][nt][0], acc[mt][nt][1]);
            float2 v1 = make_float2(acc[mt][nt][2], acc[mt][nt][3]);
            if (BIAS) {
                float b0 = bias[n], b1 = bias[n + 1];
                v0.x += b0; v0.y += b1; v1.x += b0; v1.y += b1;
            }
            *(float2*)(C + (size_t)m * N + n) = v0;
            *(float2*)(C + (size_t)(m + 8) * N + n) = v1;
        }
}

// ---------------- Fused pooling (levels 1..7 in one kernel) ----------------
// grid: (32 chunks, 32 bh). Chunk = 64 level-1 rows = 128 base rows.
__global__ __launch_bounds__(256)
void pool_fused(const float* __restrict__ qkv)
{
    __shared__ float sA[64][192];   // [row][q:0..63 | k:64..127 | v:128..191]
    __shared__ float sB[32][192];

    int c  = blockIdx.x;
    int bh = blockIdx.y;
    int b = bh >> 3, h = bh & 7;
    int tid = threadIdx.x;
    int d = tid & 63, seg = tid >> 6;
    size_t poolbase = (size_t)bh * (POOLROWS * 64);

    // Level 1
    for (int i = 0; i < 16; i++) {
        int li = seg * 16 + i;                       // local l1 row 0..63
        int grow = c * 128 + 2 * li;                 // base row in [0,4096)
        size_t base = ((size_t)(b * 4096 + grow)) * QKVW + h * 64 + d;
        float q = 0.0625f * (qkv[base] + qkv[base + QKVW]);
        float k = 0.5f * (qkv[base + 512] + qkv[base + 512 + QKVW]);
        float v = qkv[base + 1024] + qkv[base + 1024 + QKVW];
        sA[li][d] = q; sA[li][64 + d] = k; sA[li][128 + d] = v;
        size_t dst = poolbase + (size_t)(c * 64 + li) * 64 + d;
        g_poolq[dst] = q; g_poolk[dst] = k; g_poolv[dst] = v;
    }
    __syncthreads();

    // Levels 2..7
    for (int l = 2; l <= 7; l++) {
        int nl = 64 >> (l - 1);                      // local rows at this level
        int offL = 4096 - (8192 >> l);
        bool srcA = (l & 1) == 0;                    // l even: src=A, dst=B
        for (int idx = tid; idx < nl * 64; idx += 256) {
            int i = idx >> 6, dd = idx & 63;
            float q0, q1, k0, k1, v0, v1;
            if (srcA) {
                q0 = sA[2 * i][dd];       q1 = sA[2 * i + 1][dd];
                k0 = sA[2 * i][64 + dd];  k1 = sA[2 * i + 1][64 + dd];
                v0 = sA[2 * i][128 + dd]; v1 = sA[2 * i + 1][128 + dd];
            } else {
                q0 = sB[2 * i][dd];       q1 = sB[2 * i + 1][dd];
                k0 = sB[2 * i][64 + dd];  k1 = sB[2 * i + 1][64 + dd];
                v0 = sB[2 * i][128 + dd]; v1 = sB[2 * i + 1][128 + dd];
            }
            float q = 0.5f * (q0 + q1);
            float k = 0.5f * (k0 + k1);
            float v = v0 + v1;
            if (srcA) { sB[i][dd] = q; sB[i][64 + dd] = k; sB[i][128 + dd] = v; }
            else      { sA[i][dd] = q; sA[i][64 + dd] = k; sA[i][128 + dd] = v; }
            size_t dst = poolbase + (size_t)(offL + c * nl + i) * 64 + dd;
            g_poolq[dst] = q; g_poolk[dst] = k; g_poolv[dst] = v;
        }
        __syncthreads();
    }
}

// ---------------- Block attention ----------------
__global__ __launch_bounds__(128)
void attn_blocks(const float* __restrict__ qkv)
{
    __shared__ __align__(16) float sk[4][16 * 68];
    __shared__ __align__(16) float sv[4][16 * 68];
    int warp = threadIdx.x >> 5;
    int lane = threadIdx.x & 31;
    int wg = blockIdx.x * 4 + warp;

    int bh = wg / 510;
    int r  = wg - bh * 510;
    int level = 0, nb = 256;
    while (r >= nb) { r -= nb; nb >>= 1; level++; }
    int blk = r;
    int b = bh >> 3, h = bh & 7;
    int kblk = (level == 0) ? blk : (blk ^ 1);

    float* ks = sk[warp];
    float* vs = sv[warp];

    if (level == 0) {
        for (int idx = lane; idx < 1024; idx += 32) {
            int j = idx >> 6, d = idx & 63;
            size_t gk = ((size_t)(b * 4096 + kblk * 16 + j)) * QKVW + h * 64 + d;
            size_t gv = ((size_t)(b * 4096 + blk  * 16 + j)) * QKVW + h * 64 + d;
            ks[j * 68 + d] = qkv[gk + 512];
            vs[j * 68 + d] = qkv[gv + 1024];
        }
    } else {
        int off = 4096 - (8192 >> level);
        const float* kp = g_poolk + (size_t)bh * (POOLROWS * 64) + (size_t)(off + kblk * 16) * 64;
        const float* vp = g_poolv + (size_t)bh * (POOLROWS * 64) + (size_t)(off + blk  * 16) * 64;
        for (int idx = lane; idx < 1024; idx += 32) {
            int j = idx >> 6, d = idx & 63;
            ks[j * 68 + d] = kp[idx];
            vs[j * 68 + d] = vp[idx];
        }
    }

    int qi = lane >> 1, hh = lane & 1, dbase = hh * 32;
    float qr[32];
    if (level == 0) {
        const float* qp = qkv + ((size_t)(b * 4096 + blk * 16 + qi)) * QKVW + h * 64 + dbase;
#pragma unroll
        for (int t = 0; t < 32; t++) qr[t] = 0.125f * qp[t];
    } else {
        int off = 4096 - (8192 >> level);
        const float* qp = g_poolq + (size_t)bh * (POOLROWS * 64)
                        + (size_t)(off + blk * 16 + qi) * 64 + dbase;
#pragma unroll
        for (int t = 0; t < 32; t++) qr[t] = qp[t];
    }
    __syncwarp();

    float Aij[16];
#pragma unroll
    for (int j = 0; j < 16; j++) {
        float p = 0.f;
        const float* kr = ks + j * 68 + dbase;
#pragma unroll
        for (int t = 0; t < 32; t++) p += qr[t] * kr[t];
        p += __shfl_xor_sync(0xffffffffu, p, 1);
        Aij[j] = expf(p);
    }
    float asum = 0.f;
#pragma unroll
    for (int j = 0; j < 16; j++) asum += Aij[j];

    float ya[32];
#pragma unroll
    for (int t = 0; t < 32; t++) ya[t] = 0.f;
#pragma unroll
    for (int j = 0; j < 16; j++) {
        float a = Aij[j];
        const float* vr = vs + j * 68 + dbase;
#pragma unroll
        for (int t = 0; t < 32; t++) ya[t] += a * vr[t];
    }

    int yoff = 8192 - (8192 >> level);
    size_t yrow = (size_t)bh * (YROWS * 64) + (size_t)(yoff + blk * 16 + qi) * 64 + dbase;
#pragma unroll
    for (int t = 0; t < 32; t++) g_Y[yrow + t] = ya[t];
    if (hh == 0)
        g_Asum[(size_t)bh * YROWS + yoff + blk * 16 + qi] = asum;
}

// ---------------- Combine (emits bf16 hi/lo att planes) ----------------
__global__ void combine_kernel()
{
    int tid = blockIdx.x * blockDim.x + threadIdx.x;
    int c = tid & 511;
    int m = tid >> 9;
    int h = c >> 6, d = c & 63;
    int b = m >> 12, n = m & 4095;
    int bh = b * 8 + h;

    float ysum = 0.f, asum = 0.f;
#pragma unroll
    for (int l = 0; l < 8; l++) {
        int yoff = 8192 - (8192 >> l);
        int p = n >> l;
        ysum += g_Y[(size_t)bh * (YROWS * 64) + (size_t)(yoff + p) * 64 + d];
        asum += g_Asum[(size_t)bh * YROWS + yoff + p];
    }
    float val = ysum / (asum + 1e-8f);
    __nv_bfloat16 hb = __float2bfloat16_rn(val);
    __nv_bfloat16 lb = __float2bfloat16_rn(val - __bfloat162float(hb));
    g_atth[tid] = hb;
    g_attl[tid] = lb;
}

// ---------------- Launch ----------------
extern "C" void kernel_launch(void* const* d_in, const int* in_sizes, int n_in,
                              void* d_out, int out_size)
{
    const float* x     = (const float*)d_in[0];
    const float* w_qkv = (const float*)d_in[1];
    const float* w_out = (const float*)d_in[2];
    const float* b_out = (const float*)d_in[3];
    float* out = (float*)d_out;

    float* qkv_ptr;
    cudaGetSymbolAddress((void**)&qkv_ptr, g_qkv);
    __nv_bfloat16 *xh, *xl, *wqh, *wql, *woh, *wol, *ath, *atl;
    cudaGetSymbolAddress((void**)&xh, g_xh);
    cudaGetSymbolAddress((void**)&xl, g_xl);
    cudaGetSymbolAddress((void**)&wqh, g_wqh);
    cudaGetSymbolAddress((void**)&wql, g_wql);
    cudaGetSymbolAddress((void**)&woh, g_woh);
    cudaGetSymbolAddress((void**)&wol, g_wol);
    cudaGetSymbolAddress((void**)&ath, g_atth);
    cudaGetSymbolAddress((void**)&atl, g_attl);

    cudaFuncSetAttribute(gemm_bf16<0>, cudaFuncAttributeMaxDynamicSharedMemorySize, GS_SMEM);
    cudaFuncSetAttribute(gemm_bf16<1>, cudaFuncAttributeMaxDynamicSharedMemorySize, GS_SMEM);

    // 1) Convert inputs to bf16 hi/lo planes
    convert_all<<<18432, 256>>>(x, w_qkv, w_out);

    // 2) QKV projection
    gemm_bf16<0><<<dim3(QKVW / 128, NROWS / 128), 256, GS_SMEM>>>(
        xh, xl, wqh, wql, nullptr, qkv_ptr, NROWS, QKVW, 1024);

    // 3) Fused pooling
    pool_fused<<<dim3(32, 32), 256>>>(qkv_ptr);

    // 4) Block attention
    attn_blocks<<<4080, 128>>>(qkv_ptr);

    // 5) Combine + normalize + relayout (-> bf16 hi/lo)
    combine_kernel<<<(NROWS * 512) / 256, 256>>>();

    // 6) Output projection
    gemm_bf16<1><<<dim3(1024 / 128, NROWS / 128), 256, GS_SMEM>>>(
        ath, atl, woh, wol, b_out, out, NROWS, 1024, 512);
}

// round 5
// speedup vs baseline: 2.5813x; 1.1259x over previous
#include <cuda_runtime.h>
#include <cuda_bf16.h>
#include <cstdint>

// ---------------- Problem constants ----------------
#define NROWS   16384
#define QKVW    1536
#define POOLROWS 4064
#define YROWS    8160

// ---------------- Device scratch ----------------
__device__ __align__(16) float g_qkv[(size_t)NROWS * QKVW];
__device__ __align__(16) float g_poolq[(size_t)32 * POOLROWS * 64];
__device__ __align__(16) float g_poolk[(size_t)32 * POOLROWS * 64];
__device__ __align__(16) float g_poolv[(size_t)32 * POOLROWS * 64];
__device__ __align__(16) float g_Y[(size_t)32 * YROWS * 64];
__device__ __align__(16) float g_Asum[(size_t)32 * YROWS];

// bf16 hi/lo planes
__device__ __align__(16) __nv_bfloat16 g_xh[(size_t)NROWS * 1024];
__device__ __align__(16) __nv_bfloat16 g_xl[(size_t)NROWS * 1024];
__device__ __align__(16) __nv_bfloat16 g_wqh[(size_t)QKVW * 1024];
__device__ __align__(16) __nv_bfloat16 g_wql[(size_t)QKVW * 1024];
__device__ __align__(16) __nv_bfloat16 g_woh[(size_t)1024 * 512];
__device__ __align__(16) __nv_bfloat16 g_wol[(size_t)1024 * 512];
__device__ __align__(16) __nv_bfloat16 g_atth[(size_t)NROWS * 512];
__device__ __align__(16) __nv_bfloat16 g_attl[(size_t)NROWS * 512];

// ---------------- helpers ----------------
__device__ __forceinline__ uint32_t smem_to_u32(const void* p) {
    uint32_t a;
    asm("{ .reg .u64 t; cvta.to.shared.u64 t, %1; cvt.u32.u64 %0, t; }" : "=r"(a) : "l"(p));
    return a;
}
__device__ __forceinline__ uint32_t sw128(uint32_t off) {
    return off ^ ((off >> 3) & 0x70);
}

#define LDSM_X4(r0, r1, r2, r3, addr) \
    asm volatile("ldmatrix.sync.aligned.m8n8.x4.shared.b16 {%0,%1,%2,%3}, [%4];" \
        : "=r"(r0), "=r"(r1), "=r"(r2), "=r"(r3) : "r"(addr))

__device__ __forceinline__ void mma16816(float* c, const uint32_t* a, const uint32_t* b) {
    asm volatile(
        "mma.sync.aligned.m16n8k16.row.col.f32.bf16.bf16.f32 "
        "{%0,%1,%2,%3}, {%4,%5,%6,%7}, {%8,%9}, {%0,%1,%2,%3};"
        : "+f"(c[0]), "+f"(c[1]), "+f"(c[2]), "+f"(c[3])
        : "r"(a[0]), "r"(a[1]), "r"(a[2]), "r"(a[3]), "r"(b[0]), "r"(b[1]));
}

__device__ __forceinline__ void split4(float4 v, uint2& hi, uint2& lo) {
    float f[4] = {v.x, v.y, v.z, v.w};
    uint32_t h[4], l[4];
#pragma unroll
    for (int i = 0; i < 4; i++) {
        __nv_bfloat16 hb = __float2bfloat16_rn(f[i]);
        float res = f[i] - __bfloat162float(hb);
        __nv_bfloat16 lb = __float2bfloat16_rn(res);
        h[i] = (uint32_t)__bfloat16_as_ushort(hb);
        l[i] = (uint32_t)__bfloat16_as_ushort(lb);
    }
    hi.x = h[0] | (h[1] << 16); hi.y = h[2] | (h[3] << 16);
    lo.x = l[0] | (l[1] << 16); lo.y = l[2] | (l[3] << 16);
}

// ---------------- one-shot fp32 -> bf16 hi/lo conversion ----------------
__global__ __launch_bounds__(256)
void convert_all(const float* __restrict__ x, const float* __restrict__ wq,
                 const float* __restrict__ wo)
{
    int q = blockIdx.x * 256 + threadIdx.x;
    const float* src;
    uint2 *dh, *dl;
    int local;
    if (q < 4194304) {
        src = x; dh = (uint2*)g_xh; dl = (uint2*)g_xl; local = q;
    } else if (q < 4194304 + 393216) {
        src = wq; dh = (uint2*)g_wqh; dl = (uint2*)g_wql; local = q - 4194304;
    } else {
        src = wo; dh = (uint2*)g_woh; dl = (uint2*)g_wol; local = q - 4194304 - 393216;
    }
    float4 v = *(const float4*)(src + (size_t)local * 4);
    uint2 hi, lo; split4(v, hi, lo);
    dh[local] = hi; dl[local] = lo;
}

// ---------------- mma.sync GEMM: 256x128 tile, BK=64, cp.async 2-stage -----
// Stage (96KB): Ah @0 (32K), Al @32768 (32K), Bh @65536 (16K), Bl @81920 (16K)
#define GS_STAGE 98304
#define GS_SMEM  (2 * GS_STAGE)

template <int BIAS>
__global__ __launch_bounds__(256, 1)
void gemm_bf16(const __nv_bfloat16* __restrict__ Ah, const __nv_bfloat16* __restrict__ Al,
               const __nv_bfloat16* __restrict__ Bh, const __nv_bfloat16* __restrict__ Bl,
               const float* __restrict__ bias, float* __restrict__ C,
               int M, int N, int K)
{
    extern __shared__ __align__(1024) char smem[];
    const uint32_t smu = smem_to_u32(smem);
    const int tid = threadIdx.x;
    const int wid = tid >> 5, lane = tid & 31;
    const int warpM = wid & 3, warpN = wid >> 2;     // 4 x 2 warps, 64x64 tiles
    const int row0 = blockIdx.y * 256;
    const int col0 = blockIdx.x * 128;
    const int KS = K >> 6;

    float acc[4][8][4];
#pragma unroll
    for (int i = 0; i < 4; i++)
#pragma unroll
        for (int j = 0; j < 8; j++)
#pragma unroll
            for (int t = 0; t < 4; t++) acc[i][j][t] = 0.f;

    auto prefetch = [&](int ks, int buf) {
        uint32_t sb = smu + (uint32_t)buf * GS_STAGE;
        int q = tid & 7;
        int rbase = tid >> 3;
        const __nv_bfloat16* pA[2] = { Ah + (size_t)row0 * K + ks * 64,
                                       Al + (size_t)row0 * K + ks * 64 };
        const __nv_bfloat16* pB[2] = { Bh + (size_t)col0 * K + ks * 64,
                                       Bl + (size_t)col0 * K + ks * 64 };
#pragma unroll
        for (int pl = 0; pl < 2; pl++) {
#pragma unroll
            for (int i = 0; i < 8; i++) {
                int r = (i << 5) + rbase;
                const void* gp = pA[pl] + (size_t)r * K + q * 8;
                uint32_t sa = sb + pl * 32768 + sw128((uint32_t)(r * 128 + q * 16));
                asm volatile("cp.async.cg.shared.global [%0], [%1], 16;" :: "r"(sa), "l"(gp));
            }
        }
#pragma unroll
        for (int pl = 0; pl < 2; pl++) {
#pragma unroll
            for (int i = 0; i < 4; i++) {
                int r = (i << 5) + rbase;
                const void* gp = pB[pl] + (size_t)r * K + q * 8;
                uint32_t sa = sb + 65536 + pl * 16384 + sw128((uint32_t)(r * 128 + q * 16));
                asm volatile("cp.async.cg.shared.global [%0], [%1], 16;" :: "r"(sa), "l"(gp));
            }
        }
    };

    auto compute_k16 = [&](uint32_t sbase, int kk) {
        uint32_t ah[4][4], al[4][4], bh[4][4], bl[4][4];
        int aRow = warpM * 64 + (lane & 15);
        int aK2 = (kk * 16 + ((lane & 16) ? 8 : 0)) * 2;
#pragma unroll
        for (int mt = 0; mt < 4; mt++) {
            uint32_t off = sw128((uint32_t)((aRow + mt * 16) * 128 + aK2));
            LDSM_X4(ah[mt][0], ah[mt][1], ah[mt][2], ah[mt][3], sbase + off);
            LDSM_X4(al[mt][0], al[mt][1], al[mt][2], al[mt][3], sbase + 32768 + off);
        }
        int bRow = warpN * 64 + (lane & 7) + ((lane & 16) ? 8 : 0);
        int bK2 = (kk * 16 + ((lane & 8) ? 8 : 0)) * 2;
#pragma unroll
        for (int pr = 0; pr < 4; pr++) {
            uint32_t off = sw128((uint32_t)((bRow + pr * 16) * 128 + bK2));
            LDSM_X4(bh[pr][0], bh[pr][1], bh[pr][2], bh[pr][3], sbase + 65536 + off);
            LDSM_X4(bl[pr][0], bl[pr][1], bl[pr][2], bl[pr][3], sbase + 81920 + off);
        }
#pragma unroll
        for (int mt = 0; mt < 4; mt++)
#pragma unroll
            for (int nt = 0; nt < 8; nt++) {
                const uint32_t* bhp = &bh[nt >> 1][(nt & 1) * 2];
                const uint32_t* blp = &bl[nt >> 1][(nt & 1) * 2];
                mma16816(acc[mt][nt], ah[mt], bhp);
                mma16816(acc[mt][nt], ah[mt], blp);
                mma16816(acc[mt][nt], al[mt], bhp);
            }
    };

    prefetch(0, 0);
    asm volatile("cp.async.commit_group;" ::: "memory");
    prefetch(1, 1);
    asm volatile("cp.async.commit_group;" ::: "memory");

    for (int ks = 0; ks < KS; ks++) {
        asm volatile("cp.async.wait_group 1;" ::: "memory");
        __syncthreads();
        uint32_t sbase = smu + (uint32_t)(ks & 1) * GS_STAGE;
#pragma unroll
        for (int kk = 0; kk < 4; kk++) compute_k16(sbase, kk);
        __syncthreads();
        if (ks + 2 < KS) prefetch(ks + 2, ks & 1);
        asm volatile("cp.async.commit_group;" ::: "memory");
    }

    int mBase = row0 + warpM * 64 + (lane >> 2);
    int nBase = col0 + warpN * 64 + (lane & 3) * 2;
#pragma unroll
    for (int mt = 0; mt < 4; mt++)
#pragma unroll
        for (int nt = 0; nt < 8; nt++) {
            int m = mBase + mt * 16;
            int n = nBase + nt * 8;
            float2 v0 = make_float2(acc[mt][nt][0], acc[mt][nt][1]);
            float2 v1 = make_float2(acc[mt][nt][2], acc[mt][nt][3]);
            if (BIAS) {
                float b0 = bias[n], b1 = bias[n + 1];
                v0.x += b0; v0.y += b1; v1.x += b0; v1.y += b1;
            }
            *(float2*)(C + (size_t)m * N + n) = v0;
            *(float2*)(C + (size_t)(m + 8) * N + n) = v1;
        }
}

// ---------------- Fused pooling (levels 1..7) ----------------
__global__ __launch_bounds__(256)
void pool_fused(const float* __restrict__ qkv)
{
    __shared__ float sA[64][192];
    __shared__ float sB[32][192];

    int c  = blockIdx.x;
    int bh = blockIdx.y;
    int b = bh >> 3, h = bh & 7;
    int tid = threadIdx.x;
    int d = tid & 63, seg = tid >> 6;
    size_t poolbase = (size_t)bh * (POOLROWS * 64);

    for (int i = 0; i < 16; i++) {
        int li = seg * 16 + i;
        int grow = c * 128 + 2 * li;
        size_t base = ((size_t)(b * 4096 + grow)) * QKVW + h * 64 + d;
        float q = 0.0625f * (qkv[base] + qkv[base + QKVW]);
        float k = 0.5f * (qkv[base + 512] + qkv[base + 512 + QKVW]);
        float v = qkv[base + 1024] + qkv[base + 1024 + QKVW];
        sA[li][d] = q; sA[li][64 + d] = k; sA[li][128 + d] = v;
        size_t dst = poolbase + (size_t)(c * 64 + li) * 64 + d;
        g_poolq[dst] = q; g_poolk[dst] = k; g_poolv[dst] = v;
    }
    __syncthreads();

    for (int l = 2; l <= 7; l++) {
        int nl = 64 >> (l - 1);
        int offL = 4096 - (8192 >> l);
        bool srcA = (l & 1) == 0;
        for (int idx = tid; idx < nl * 64; idx += 256) {
            int i = idx >> 6, dd = idx & 63;
            float q0, q1, k0, k1, v0, v1;
            if (srcA) {
                q0 = sA[2 * i][dd];       q1 = sA[2 * i + 1][dd];
                k0 = sA[2 * i][64 + dd];  k1 = sA[2 * i + 1][64 + dd];
                v0 = sA[2 * i][128 + dd]; v1 = sA[2 * i + 1][128 + dd];
            } else {
                q0 = sB[2 * i][dd];       q1 = sB[2 * i + 1][dd];
                k0 = sB[2 * i][64 + dd];  k1 = sB[2 * i + 1][64 + dd];
                v0 = sB[2 * i][128 + dd]; v1 = sB[2 * i + 1][128 + dd];
            }
            float q = 0.5f * (q0 + q1);
            float k = 0.5f * (k0 + k1);
            float v = v0 + v1;
            if (srcA) { sB[i][dd] = q; sB[i][64 + dd] = k; sB[i][128 + dd] = v; }
            else      { sA[i][dd] = q; sA[i][64 + dd] = k; sA[i][128 + dd] = v; }
            size_t dst = poolbase + (size_t)(offL + c * nl + i) * 64 + dd;
            g_poolq[dst] = q; g_poolk[dst] = k; g_poolv[dst] = v;
        }
        __syncthreads();
    }
}

// ---------------- Block attention (vectorized float4) ----------------
// 8 warps/CTA, one warp per 16x16 block. 2040 CTAs.
__global__ __launch_bounds__(256)
void attn_blocks(const float* __restrict__ qkv)
{
    __shared__ float4 sk[8][16][16];
    __shared__ float4 sv[8][16][16];
    int warp = threadIdx.x >> 5;
    int lane = threadIdx.x & 31;
    int wg = blockIdx.x * 8 + warp;

    int bh = wg / 510;
    int r  = wg - bh * 510;
    int level = 0, nb = 256;
    while (r >= nb) { r -= nb; nb >>= 1; level++; }
    int blk = r;
    int b = bh >> 3, h = bh & 7;
    int kblk = (level == 0) ? blk : (blk ^ 1);

    if (level == 0) {
        const float* kbase = qkv + ((size_t)(b * 4096 + kblk * 16)) * QKVW + 512 + h * 64;
        const float* vbase = qkv + ((size_t)(b * 4096 + blk  * 16)) * QKVW + 1024 + h * 64;
#pragma unroll
        for (int i = 0; i < 8; i++) {
            int idx = lane + i * 32;
            int j = idx >> 4, qd = idx & 15;
            sk[warp][j][qd] = *((const float4*)(kbase + (size_t)j * QKVW) + qd);
            sv[warp][j][qd] = *((const float4*)(vbase + (size_t)j * QKVW) + qd);
        }
    } else {
        int off = 4096 - (8192 >> level);
        const float4* kp = (const float4*)(g_poolk + (size_t)bh * (POOLROWS * 64)
                                           + (size_t)(off + kblk * 16) * 64);
        const float4* vp = (const float4*)(g_poolv + (size_t)bh * (POOLROWS * 64)
                                           + (size_t)(off + blk * 16) * 64);
#pragma unroll
        for (int i = 0; i < 8; i++) {
            int idx = lane + i * 32;
            sk[warp][0][idx] = kp[idx];   // contiguous 256 float4
            sv[warp][0][idx] = vp[idx];
        }
    }

    int qi = lane >> 1, hh = lane & 1;
    float4 qr[8];
    if (level == 0) {
        const float4* qp = (const float4*)(qkv + ((size_t)(b * 4096 + blk * 16 + qi)) * QKVW
                                           + h * 64 + hh * 32);
#pragma unroll
        for (int t = 0; t < 8; t++) {
            float4 v = qp[t];
            qr[t] = make_float4(0.125f * v.x, 0.125f * v.y, 0.125f * v.z, 0.125f * v.w);
        }
    } else {
        int off = 4096 - (8192 >> level);
        const float4* qp = (const float4*)(g_poolq + (size_t)bh * (POOLROWS * 64)
                                           + (size_t)(off + blk * 16 + qi) * 64 + hh * 32);
#pragma unroll
        for (int t = 0; t < 8; t++) qr[t] = qp[t];
    }
    __syncwarp();

    float Aij[16];
#pragma unroll
    for (int j = 0; j < 16; j++) {
        const float4* kr = &sk[warp][j][hh * 8];
        float p = 0.f;
#pragma unroll
        for (int t = 0; t < 8; t++) {
            float4 kv = kr[t];
            p += qr[t].x * kv.x + qr[t].y * kv.y + qr[t].z * kv.z + qr[t].w * kv.w;
        }
        p += __shfl_xor_sync(0xffffffffu, p, 1);
        Aij[j] = expf(p);
    }
    float asum = 0.f;
#pragma unroll
    for (int j = 0; j < 16; j++) asum += Aij[j];

    float4 ya[8];
#pragma unroll
    for (int t = 0; t < 8; t++) ya[t] = make_float4(0.f, 0.f, 0.f, 0.f);
#pragma unroll
    for (int j = 0; j < 16; j++) {
        float a = Aij[j];
        const float4* vr = &sv[warp][j][hh * 8];
#pragma unroll
        for (int t = 0; t < 8; t++) {
            float4 vv = vr[t];
            ya[t].x += a * vv.x; ya[t].y += a * vv.y;
            ya[t].z += a * vv.z; ya[t].w += a * vv.w;
        }
    }

    int yoff = 8192 - (8192 >> level);
    float4* yp = (float4*)(g_Y + (size_t)bh * (YROWS * 64)
                           + (size_t)(yoff + blk * 16 + qi) * 64 + hh * 32);
#pragma unroll
    for (int t = 0; t < 8; t++) yp[t] = ya[t];
    if (hh == 0)
        g_Asum[(size_t)bh * YROWS + yoff + blk * 16 + qi] = asum;
}

// ---------------- Combine (vectorized, emits bf16 hi/lo) ----------------
__global__ __launch_bounds__(256)
void combine_kernel()
{
    int tid = blockIdx.x * 256 + threadIdx.x;   // NROWS*128 threads
    int qd = tid & 127;                          // quad within row (h*16 + dq)
    int m  = tid >> 7;
    int h  = qd >> 4, dq = qd & 15;
    int b = m >> 12, n = m & 4095;
    int bh = b * 8 + h;

    const float4* Yb = (const float4*)(g_Y + (size_t)bh * (YROWS * 64));
    const float* Ab = g_Asum + (size_t)bh * YROWS;

    float4 ysum = make_float4(0.f, 0.f, 0.f, 0.f);
    float asum = 0.f;
#pragma unroll
    for (int l = 0; l < 8; l++) {
        int yoff = 8192 - (8192 >> l);
        int p = yoff + (n >> l);
        float4 y = Yb[(size_t)p * 16 + dq];
        ysum.x += y.x; ysum.y += y.y; ysum.z += y.z; ysum.w += y.w;
        asum += Ab[p];
    }
    float inv = 1.f / (asum + 1e-8f);
    float4 val = make_float4(ysum.x * inv, ysum.y * inv, ysum.z * inv, ysum.w * inv);
    uint2 hi, lo; split4(val, hi, lo);
    ((uint2*)g_atth)[tid] = hi;
    ((uint2*)g_attl)[tid] = lo;
}

// ---------------- Launch ----------------
extern "C" void kernel_launch(void* const* d_in, const int* in_sizes, int n_in,
                              void* d_out, int out_size)
{
    const float* x     = (const float*)d_in[0];
    const float* w_qkv = (const float*)d_in[1];
    const float* w_out = (const float*)d_in[2];
    const float* b_out = (const float*)d_in[3];
    float* out = (float*)d_out;

    float* qkv_ptr;
    cudaGetSymbolAddress((void**)&qkv_ptr, g_qkv);
    __nv_bfloat16 *xh, *xl, *wqh, *wql, *woh, *wol, *ath, *atl;
    cudaGetSymbolAddress((void**)&xh, g_xh);
    cudaGetSymbolAddress((void**)&xl, g_xl);
    cudaGetSymbolAddress((void**)&wqh, g_wqh);
    cudaGetSymbolAddress((void**)&wql, g_wql);
    cudaGetSymbolAddress((void**)&woh, g_woh);
    cudaGetSymbolAddress((void**)&wol, g_wol);
    cudaGetSymbolAddress((void**)&ath, g_atth);
    cudaGetSymbolAddress((void**)&atl, g_attl);

    cudaFuncSetAttribute(gemm_bf16<0>, cudaFuncAttributeMaxDynamicSharedMemorySize, GS_SMEM);
    cudaFuncSetAttribute(gemm_bf16<1>, cudaFuncAttributeMaxDynamicSharedMemorySize, GS_SMEM);

    // 1) Convert inputs to bf16 hi/lo planes
    convert_all<<<18432, 256>>>(x, w_qkv, w_out);

    // 2) QKV projection: [16384,1024] x [1536,1024]^T
    gemm_bf16<0><<<dim3(QKVW / 128, NROWS / 256), 256, GS_SMEM>>>(
        xh, xl, wqh, wql, nullptr, qkv_ptr, NROWS, QKVW, 1024);

    // 3) Fused pooling
    pool_fused<<<dim3(32, 32), 256>>>(qkv_ptr);

    // 4) Block attention (16320 warps / 8 per CTA)
    attn_blocks<<<2040, 256>>>(qkv_ptr);

    // 5) Combine + normalize + relayout (-> bf16 hi/lo)
    combine_kernel<<<(NROWS * 128) / 256, 256>>>();

    // 6) Output projection: [16384,512] x [1024,512]^T + bias
    gemm_bf16<1><<<dim3(1024 / 128, NROWS / 256), 256, GS_SMEM>>>(
        ath, atl, woh, wol, b_out, out, NROWS, 1024, 512);
}